// round 12
// baseline (speedup 1.0000x reference)
#include <cuda_runtime.h>
#include <cuda_fp16.h>
#include <cstdint>

#define NN   100000
#define EE   3200000
#define FIN  256
#define HH   512
#define FOUT 256

#define BM 128
#define BN 128
#define BKH 64
#define STAGES 3
#define STAGE_BYTES 32768
#define SMEM_BYTES (STAGES * STAGE_BYTES)

#define ACT_SCALE   0.00390625f   /* 2^-8 */
#define ACT_UNSCALE 256.0f

#define SW(o) ((o) ^ (((o) >> 3) & 0x70))
#define SPMM_GRID ((NN + 7) / 8)

// ---------------- scratch ---------------------------------------------------
__device__ __half g_X0h[(size_t)NN * FIN];
__device__ __half g_X1[(size_t)NN * HH];
__device__ __half g_X2[(size_t)NN * HH];
__device__ __half g_HA[(size_t)NN * HH];
__device__ __half g_HB[(size_t)NN * HH];
__device__ __half g_Z [(size_t)NN * 768];
__device__ __half g_B1[512 * 768];
__device__ __half g_B2[512 * 1536];
__device__ __half g_B3[512 * 1536];
__device__ __half g_B4[768 * 512];
__device__ int    g_rowptr[NN + 1];
__device__ int    g_cnt[NN];
__device__ int    g_col[EE];
__device__ float  g_wgt[EE];

// ---------------- helpers ---------------------------------------------------
__device__ __forceinline__ uint32_t smem_u32(const void* p) {
    uint32_t a;
    asm("{ .reg .u64 t; cvta.to.shared.u64 t, %1; cvt.u32.u64 %0, t; }" : "=r"(a) : "l"(p));
    return a;
}

template <int N>
__device__ __forceinline__ void cp_wait_group() {
    asm volatile("cp.async.wait_group %0;" :: "n"(N) : "memory");
}

__device__ __forceinline__ void cp16(uint32_t dst, const void* src) {
    asm volatile("cp.async.cg.shared.global [%0], [%1], 16;" :: "r"(dst), "l"(src));
}

__device__ __forceinline__ void ldsm4(uint32_t* r, uint32_t addr) {
    asm volatile("ldmatrix.sync.aligned.m8n8.x4.shared.b16 {%0,%1,%2,%3}, [%4];"
                 : "=r"(r[0]), "=r"(r[1]), "=r"(r[2]), "=r"(r[3]) : "r"(addr));
}

__device__ __forceinline__ void mma_f16(float* c, const uint32_t* a,
                                        uint32_t b0, uint32_t b1) {
    asm volatile(
        "mma.sync.aligned.m16n8k16.row.col.f32.f16.f16.f32 "
        "{%0,%1,%2,%3}, {%4,%5,%6,%7}, {%8,%9}, {%0,%1,%2,%3};"
        : "+f"(c[0]), "+f"(c[1]), "+f"(c[2]), "+f"(c[3])
        : "r"(a[0]), "r"(a[1]), "r"(a[2]), "r"(a[3]), "r"(b0), "r"(b1));
}

__device__ __forceinline__ void acc_edge(float* acc, float wv, uint4 v) {
    float2 f0 = __half22float2(*(__half2*)&v.x);
    float2 f1 = __half22float2(*(__half2*)&v.y);
    float2 f2 = __half22float2(*(__half2*)&v.z);
    float2 f3 = __half22float2(*(__half2*)&v.w);
    acc[0] += wv * f0.x; acc[1] += wv * f0.y;
    acc[2] += wv * f1.x; acc[3] += wv * f1.y;
    acc[4] += wv * f2.x; acc[5] += wv * f2.y;
    acc[6] += wv * f3.x; acc[7] += wv * f3.y;
}

// ---------------- CSR build -------------------------------------------------
__global__ void zero_cnt_kernel() {
    int i = blockIdx.x * blockDim.x + threadIdx.x;
    if (i < NN) g_cnt[i] = 0;
}

__global__ void count_kernel(const int* __restrict__ rows) {
    int i = blockIdx.x * blockDim.x + threadIdx.x;
    if (i < EE) atomicAdd(&g_cnt[rows[i]], 1);
}

// warp-shuffle hierarchical scan, 4 elems/thread, 4096 per iteration
__global__ void scan_kernel() {
    __shared__ int wsum[32];
    __shared__ int carry;
    int tid  = threadIdx.x;
    int lane = tid & 31;
    int wid  = tid >> 5;
    if (tid == 0) carry = 0;
    __syncthreads();
    for (int base = 0; base < NN; base += 4096) {
        int i0 = base + tid * 4;
        int v[4];
        #pragma unroll
        for (int k = 0; k < 4; k++) {
            int i = i0 + k;
            v[k] = (i < NN) ? g_cnt[i] : 0;
        }
        int s = v[0] + v[1] + v[2] + v[3];
        int sc = s;
        #pragma unroll
        for (int off = 1; off < 32; off <<= 1) {
            int t = __shfl_up_sync(0xffffffffu, sc, off);
            if (lane >= off) sc += t;
        }
        if (lane == 31) wsum[wid] = sc;
        __syncthreads();
        if (wid == 0) {
            int ws = wsum[lane];
            #pragma unroll
            for (int off = 1; off < 32; off <<= 1) {
                int t = __shfl_up_sync(0xffffffffu, ws, off);
                if (lane >= off) ws += t;
            }
            wsum[lane] = ws;
        }
        __syncthreads();
        int warpoff = (wid > 0) ? wsum[wid - 1] : 0;
        int excl = carry + warpoff + (sc - s);
        #pragma unroll
        for (int k = 0; k < 4; k++) {
            int i = i0 + k;
            if (i < NN) { g_rowptr[i] = excl; g_cnt[i] = excl; }
            excl += v[k];
        }
        __syncthreads();
        if (tid == 0) carry += wsum[31];
        __syncthreads();
    }
    if (tid == 0) g_rowptr[NN] = carry;
}

__global__ void scatter_kernel(const int* __restrict__ rows,
                               const int* __restrict__ cols,
                               const float* __restrict__ w) {
    int i = blockIdx.x * blockDim.x + threadIdx.x;
    if (i < EE) {
        int r = rows[i];
        int p = atomicAdd(&g_cnt[r], 1);
        g_col[p] = cols[i];
        g_wgt[p] = w[i];
    }
}

// ---------------- SpMM: y[r] = alpha*(L x)[r] + beta*s[r] (fp16 io) --------
// 256 threads = 8 warps = 8 rows per block; shfl-broadcast edge staging.
__global__ __launch_bounds__(256)
void spmm_kernel(const __half* __restrict__ x, int sx,
                 const __half* __restrict__ sub, int ss,
                 __half* __restrict__ y, int sy,
                 float alpha, float beta) {
    int warp = threadIdx.x >> 5;
    int lane = threadIdx.x & 31;
    int r = blockIdx.x * 8 + warp;
    if (r >= NN) return;
    int beg = g_rowptr[r];
    int end = g_rowptr[r + 1];
    int fo = lane * 8;
    float acc[8] = {0.f, 0.f, 0.f, 0.f, 0.f, 0.f, 0.f, 0.f};
    for (int base = beg; base < end; base += 32) {
        int m = min(32, end - base);
        int   ce = 0;
        float we = 0.f;
        if (lane < m) { ce = g_col[base + lane]; we = g_wgt[base + lane]; }
        #pragma unroll 4
        for (int j = 0; j < m; j++) {
            int   cj = __shfl_sync(0xffffffffu, ce, j);
            float wj = __shfl_sync(0xffffffffu, we, j);
            uint4 v = *(const uint4*)(x + (size_t)cj * sx + fo);
            acc_edge(acc, wj, v);
        }
    }
    float o[8];
    #pragma unroll
    for (int i = 0; i < 8; i++) o[i] = alpha * acc[i];
    if (sub != nullptr) {
        uint4 sv = *(const uint4*)(sub + (size_t)r * ss + fo);
        float2 s0 = __half22float2(*(__half2*)&sv.x);
        float2 s1 = __half22float2(*(__half2*)&sv.y);
        float2 s2 = __half22float2(*(__half2*)&sv.z);
        float2 s3 = __half22float2(*(__half2*)&sv.w);
        o[0] += beta * s0.x; o[1] += beta * s0.y;
        o[2] += beta * s1.x; o[3] += beta * s1.y;
        o[4] += beta * s2.x; o[5] += beta * s2.y;
        o[6] += beta * s3.x; o[7] += beta * s3.y;
    }
    uint4 ov;
    *(__half2*)&ov.x = __floats2half2_rn(o[0], o[1]);
    *(__half2*)&ov.y = __floats2half2_rn(o[2], o[3]);
    *(__half2*)&ov.z = __floats2half2_rn(o[4], o[5]);
    *(__half2*)&ov.w = __floats2half2_rn(o[6], o[7]);
    *(uint4*)(y + (size_t)r * sy + fo) = ov;
}

// ---------------- final SpMM: out = 256*(L v + z0 - z2) + bias (fp32 out) --
__global__ __launch_bounds__(256)
void spmm_final_kernel(const __half* __restrict__ v,
                       const __half* __restrict__ Z,
                       const float* __restrict__ bias,
                       float* __restrict__ out) {
    int warp = threadIdx.x >> 5;
    int lane = threadIdx.x & 31;
    int r = blockIdx.x * 8 + warp;
    if (r >= NN) return;
    int beg = g_rowptr[r];
    int end = g_rowptr[r + 1];
    int fo = lane * 8;
    float acc[8] = {0.f, 0.f, 0.f, 0.f, 0.f, 0.f, 0.f, 0.f};
    for (int base = beg; base < end; base += 32) {
        int m = min(32, end - base);
        int   ce = 0;
        float we = 0.f;
        if (lane < m) { ce = g_col[base + lane]; we = g_wgt[base + lane]; }
        #pragma unroll 4
        for (int j = 0; j < m; j++) {
            int   cj = __shfl_sync(0xffffffffu, ce, j);
            float wj = __shfl_sync(0xffffffffu, we, j);
            uint4 vv = *(const uint4*)(v + (size_t)cj * FOUT + fo);
            acc_edge(acc, wj, vv);
        }
    }
    uint4 z0v = *(const uint4*)(Z + (size_t)r * 768 + fo);
    uint4 z2v = *(const uint4*)(Z + (size_t)r * 768 + 512 + fo);
    const __half* z0 = (const __half*)&z0v;
    const __half* z2 = (const __half*)&z2v;
    float res[8];
    #pragma unroll
    for (int i = 0; i < 8; i++)
        res[i] = ACT_UNSCALE * (acc[i] + __half2float(z0[i]) - __half2float(z2[i]))
               + bias[fo + i];
    *(float4*)(out + (size_t)r * FOUT + fo)     = make_float4(res[0], res[1], res[2], res[3]);
    *(float4*)(out + (size_t)r * FOUT + fo + 4) = make_float4(res[4], res[5], res[6], res[7]);
}

// ---------------- weight de-interleave --------------------------------------
__global__ void split_kernel(const float* __restrict__ W, __half* __restrict__ B,
                             int F, int Hdim) {
    int idx = blockIdx.x * blockDim.x + threadIdx.x;
    int tot = 3 * F * Hdim;
    if (idx < tot) {
        int kk = idx % (3 * F);
        int o  = idx / (3 * F);
        int seg = kk / F;
        int f   = kk % F;
        B[idx] = __float2half_rn(W[(size_t)o * (3 * F) + f * 3 + seg]);
    }
}

__global__ void split4_kernel(const float* __restrict__ W, __half* __restrict__ B) {
    int idx = blockIdx.x * blockDim.x + threadIdx.x;
    if (idx < 768 * 512) {
        int k = idx % 512;
        int r = idx / 512;
        int seg = r / 256;
        int o   = r % 256;
        B[idx] = __float2half_rn(W[(size_t)o * 1536 + k * 3 + seg]);
    }
}

__global__ void round_kernel(const float* __restrict__ in, __half* __restrict__ out, int n) {
    int i = blockIdx.x * blockDim.x + threadIdx.x;
    if (i < n) out[i] = __float2half_rn(in[i] * ACT_SCALE);
}

// ---------------- mma.sync fp16 GEMM -----------------------------------------
__device__ __forceinline__ void load_tile(uint32_t sb, int s, int kt,
                                          const __half* __restrict__ A0,
                                          const __half* __restrict__ A1,
                                          const __half* __restrict__ A2,
                                          const __half* __restrict__ Bt,
                                          int n, int F, int Ktot,
                                          int bm, int bn, int tid) {
    int kg  = kt * BKH;
    int seg = kg / F;
    const __half* Ap = (seg == 0) ? A0 : ((seg == 1) ? A1 : A2);
    int kin = kg - seg * F;
    uint32_t abase = sb + s * STAGE_BYTES;
    uint32_t bbase = abase + 16384;
    #pragma unroll
    for (int i = 0; i < 4; i++) {
        int lin = i * 256 + tid;
        int row = lin >> 3;
        int c16 = lin & 7;
        int gr = bm + row;
        if (gr >= n) gr = n - 1;
        uint32_t off = row * 128 + c16 * 16;
        cp16(abase + SW(off), Ap + (size_t)gr * F + kin + c16 * 8);
    }
    #pragma unroll
    for (int i = 0; i < 4; i++) {
        int lin = i * 256 + tid;
        int row = lin >> 3;
        int c16 = lin & 7;
        uint32_t off = row * 128 + c16 * 16;
        cp16(bbase + SW(off), Bt + (size_t)(bn + row) * Ktot + kg + c16 * 8);
    }
}

template <bool RELU>
__global__ __launch_bounds__(256, 2)
void gemm_mma_kernel(const __half* __restrict__ A0,
                     const __half* __restrict__ A1,
                     const __half* __restrict__ A2,
                     const __half* __restrict__ Bt,
                     const float* __restrict__ bias,
                     __half* __restrict__ C,
                     int n, int F, int Ktot, int Hdim,
                     float bias_scale) {
    extern __shared__ char smem[];
    uint32_t sb = smem_u32(smem);
    int tid  = threadIdx.x;
    int lane = tid & 31;
    int wid  = tid >> 5;
    int wm = wid & 1;
    int wn = wid >> 1;
    int bn = blockIdx.x * BN;
    int bm = blockIdx.y * BM;
    int T = Ktot / BKH;

    float c[4][4][4];
    #pragma unroll
    for (int mi = 0; mi < 4; mi++)
        #pragma unroll
        for (int j = 0; j < 4; j++)
            #pragma unroll
            for (int e = 0; e < 4; e++) c[mi][j][e] = 0.f;

    #pragma unroll
    for (int p = 0; p < STAGES - 1; p++) {
        load_tile(sb, p, p, A0, A1, A2, Bt, n, F, Ktot, bm, bn, tid);
        asm volatile("cp.async.commit_group;" ::: "memory");
    }

    int lrow16 = lane & 15;
    int lhalf  = (lane >> 4) << 4;

    for (int t = 0; t < T; t++) {
        cp_wait_group<STAGES - 2>();
        __syncthreads();
        int pt = t + STAGES - 1;
        if (pt < T)
            load_tile(sb, pt % STAGES, pt, A0, A1, A2, Bt, n, F, Ktot, bm, bn, tid);
        asm volatile("cp.async.commit_group;" ::: "memory");

        uint32_t abase = sb + (t % STAGES) * STAGE_BYTES;
        uint32_t bbase = abase + 16384;

        #pragma unroll
        for (int ks = 0; ks < 4; ks++) {
            int colb = ks * 32 + lhalf;
            uint32_t a[4][4];
            #pragma unroll
            for (int mi = 0; mi < 4; mi++) {
                uint32_t off = (uint32_t)((wm * 64 + mi * 16 + lrow16) * 128 + colb);
                ldsm4(a[mi], abase + SW(off));
            }
            uint32_t b[2][4];
            #pragma unroll
            for (int p = 0; p < 2; p++) {
                uint32_t off = (uint32_t)((wn * 32 + p * 16 + lrow16) * 128 + colb);
                ldsm4(b[p], bbase + SW(off));
            }
            #pragma unroll
            for (int mi = 0; mi < 4; mi++)
                #pragma unroll
                for (int j = 0; j < 4; j++)
                    mma_f16(c[mi][j], a[mi], b[j >> 1][j & 1], b[j >> 1][2 + (j & 1)]);
        }
    }

    #pragma unroll
    for (int mi = 0; mi < 4; mi++) {
        int r0 = bm + wm * 64 + mi * 16 + (lane >> 2);
        #pragma unroll
        for (int j = 0; j < 4; j++) {
            int col = bn + wn * 32 + j * 8 + (lane & 3) * 2;
            float bb0 = bias[col] * bias_scale;
            float bb1 = bias[col + 1] * bias_scale;
            #pragma unroll
            for (int h = 0; h < 2; h++) {
                int r = r0 + h * 8;
                if (r < n) {
                    float v0 = c[mi][j][2 * h]     + bb0;
                    float v1 = c[mi][j][2 * h + 1] + bb1;
                    if (RELU) { v0 = fmaxf(v0, 0.f); v1 = fmaxf(v1, 0.f); }
                    __half2* Ch = (__half2*)(C + (size_t)r * Hdim + col);
                    *Ch = __floats2half2_rn(v0, v1);
                }
            }
        }
    }
}

// ---------------- host orchestration ---------------------------------------
struct Ctx {
    cudaStream_t s2;
    cudaEvent_t ev[2];
    Ctx() {
        cudaStreamCreateWithFlags(&s2, cudaStreamNonBlocking);
        for (int i = 0; i < 2; i++)
            cudaEventCreateWithFlags(&ev[i], cudaEventDisableTiming);
    }
};
static Ctx& ctx() { static Ctx c; return c; }

static void run_hidden_layer(const __half* in, int F,
                             const __half* Bm, const float* bias,
                             __half* X1, __half* X2, __half* outp) {
    for (int c = 0; c < F / 256; c++) {
        int f0 = c * 256;
        spmm_kernel<<<SPMM_GRID, 256>>>(in + f0, F, nullptr, 0, X1 + f0, F, 1.f, 0.f);
        spmm_kernel<<<SPMM_GRID, 256>>>(X1 + f0, F, in + f0, F, X2 + f0, F, 2.f, -1.f);
    }
    dim3 grid(HH / BN, (NN + BM - 1) / BM);
    gemm_mma_kernel<true><<<grid, 256, SMEM_BYTES>>>(
        in, X1, X2, Bm, bias, outp, NN, F, 3 * F, HH, ACT_SCALE);
}

extern "C" void kernel_launch(void* const* d_in, const int* in_sizes, int n_in,
                              void* d_out, int out_size) {
    const float* x    = (const float*)d_in[0];
    const int*   er   = (const int*)d_in[1];
    const int*   ec   = (const int*)d_in[2];
    const float* ew   = (const float*)d_in[3];
    const float* W1   = (const float*)d_in[4];
    const float* b1   = (const float*)d_in[5];
    const float* W2   = (const float*)d_in[6];
    const float* b2   = (const float*)d_in[7];
    const float* W3   = (const float*)d_in[8];
    const float* b3   = (const float*)d_in[9];
    const float* Wout = (const float*)d_in[10];
    const float* bout = (const float*)d_in[11];
    float* out = (float*)d_out;

    __half *X0h, *X1, *X2, *HA, *HB, *B1, *B2, *B3, *B4, *Z;
    float* dummy_bias;
    cudaGetSymbolAddress((void**)&X0h, g_X0h);
    cudaGetSymbolAddress((void**)&X1,  g_X1);
    cudaGetSymbolAddress((void**)&X2,  g_X2);
    cudaGetSymbolAddress((void**)&HA,  g_HA);
    cudaGetSymbolAddress((void**)&HB,  g_HB);
    cudaGetSymbolAddress((void**)&B1,  g_B1);
    cudaGetSymbolAddress((void**)&B2,  g_B2);
    cudaGetSymbolAddress((void**)&B3,  g_B3);
    cudaGetSymbolAddress((void**)&B4,  g_B4);
    cudaGetSymbolAddress((void**)&Z,   g_Z);
    cudaGetSymbolAddress((void**)&dummy_bias, g_wgt);

    cudaFuncSetAttribute(gemm_mma_kernel<true>,
                         cudaFuncAttributeMaxDynamicSharedMemorySize, SMEM_BYTES);
    cudaFuncSetAttribute(gemm_mma_kernel<false>,
                         cudaFuncAttributeMaxDynamicSharedMemorySize, SMEM_BYTES);

    Ctx& cx = ctx();
    cudaStream_t s2 = cx.s2;

    // ---- fork: side stream does round + weight splits (DRAM-light) ----
    cudaEventRecord(cx.ev[0], 0);
    cudaStreamWaitEvent(s2, cx.ev[0], 0);
    round_kernel<<<(NN * FIN + 255) / 256, 256, 0, s2>>>(x, X0h, NN * FIN);
    split_kernel<<<(3 * FIN * HH + 255) / 256, 256, 0, s2>>>(W1, B1, FIN, HH);
    split_kernel<<<(3 * HH * HH + 255) / 256, 256, 0, s2>>>(W2, B2, HH, HH);
    split_kernel<<<(3 * HH * HH + 255) / 256, 256, 0, s2>>>(W3, B3, HH, HH);
    split4_kernel<<<(768 * 512 + 255) / 256, 256, 0, s2>>>(Wout, B4);
    cudaEventRecord(cx.ev[1], s2);

    // ---- main: CSR build (concurrent) ----
    zero_cnt_kernel<<<(NN + 255) / 256, 256>>>();
    count_kernel<<<(EE + 255) / 256, 256>>>(er);
    scan_kernel<<<1, 1024>>>();
    scatter_kernel<<<(EE + 255) / 256, 256>>>(er, ec, ew);
    cudaStreamWaitEvent(0, cx.ev[1], 0);

    // ---- layers 1-3 ----
    run_hidden_layer(X0h, FIN, B1, b1, X1, X2, HA);
    run_hidden_layer(HA,  HH,  B2, b2, X1, X2, HB);
    run_hidden_layer(HB,  HH,  B3, b3, X1, X2, HA);

    // ---- layer 4 (weights-first) ----
    {
        dim3 grid(768 / BN, (NN + BM - 1) / BM);
        gemm_mma_kernel<false><<<grid, 256, SMEM_BYTES>>>(
            HA, HA, HA, B4, dummy_bias, Z, NN, HH, HH, 768, 0.f);
    }
    spmm_kernel<<<SPMM_GRID, 256>>>(Z + 512, 768, Z + 256, 768, X1, FOUT, 2.f, 1.f);
    spmm_final_kernel<<<SPMM_GRID, 256>>>(X1, Z, bout, out);
}

// round 13
// speedup vs baseline: 1.0922x; 1.0922x over previous
#include <cuda_runtime.h>
#include <cuda_fp16.h>
#include <cstdint>

#define NN   100000
#define EE   3200000
#define FIN  256
#define HH   512
#define FOUT 256

#define BM 128
#define BN 128
#define BKH 64
#define STAGES 3
#define STAGE_BYTES 32768
#define SMEM_BYTES (STAGES * STAGE_BYTES)

#define ACT_SCALE   0.00390625f   /* 2^-8 */
#define ACT_UNSCALE 256.0f

#define SW(o) ((o) ^ (((o) >> 3) & 0x70))
#define SPMM_GRID ((NN + 3) / 4)

// ---------------- scratch ---------------------------------------------------
__device__ __half g_X0h[(size_t)NN * FIN];
__device__ __half g_X1[(size_t)NN * HH];
__device__ __half g_X2[(size_t)NN * HH];
__device__ __half g_HA[(size_t)NN * HH];
__device__ __half g_HB[(size_t)NN * HH];
__device__ __half g_Z [(size_t)NN * 768];
__device__ __half g_B1[512 * 768];
__device__ __half g_B2[512 * 1536];
__device__ __half g_B3[512 * 1536];
__device__ __half g_B4[768 * 512];
__device__ int    g_rowptr[NN + 1];
__device__ int    g_cnt[NN];
__device__ int    g_col[EE];
__device__ float  g_wgt[EE];

// ---------------- helpers ---------------------------------------------------
__device__ __forceinline__ uint32_t smem_u32(const void* p) {
    uint32_t a;
    asm("{ .reg .u64 t; cvta.to.shared.u64 t, %1; cvt.u32.u64 %0, t; }" : "=r"(a) : "l"(p));
    return a;
}

template <int N>
__device__ __forceinline__ void cp_wait_group() {
    asm volatile("cp.async.wait_group %0;" :: "n"(N) : "memory");
}

__device__ __forceinline__ void cp16(uint32_t dst, const void* src) {
    asm volatile("cp.async.cg.shared.global [%0], [%1], 16;" :: "r"(dst), "l"(src));
}

__device__ __forceinline__ void ldsm4(uint32_t* r, uint32_t addr) {
    asm volatile("ldmatrix.sync.aligned.m8n8.x4.shared.b16 {%0,%1,%2,%3}, [%4];"
                 : "=r"(r[0]), "=r"(r[1]), "=r"(r[2]), "=r"(r[3]) : "r"(addr));
}

__device__ __forceinline__ void mma_f16(float* c, const uint32_t* a,
                                        uint32_t b0, uint32_t b1) {
    asm volatile(
        "mma.sync.aligned.m16n8k16.row.col.f32.f16.f16.f32 "
        "{%0,%1,%2,%3}, {%4,%5,%6,%7}, {%8,%9}, {%0,%1,%2,%3};"
        : "+f"(c[0]), "+f"(c[1]), "+f"(c[2]), "+f"(c[3])
        : "r"(a[0]), "r"(a[1]), "r"(a[2]), "r"(a[3]), "r"(b0), "r"(b1));
}

__device__ __forceinline__ void acc_edge(float* acc, float wv, uint4 v) {
    float2 f0 = __half22float2(*(__half2*)&v.x);
    float2 f1 = __half22float2(*(__half2*)&v.y);
    float2 f2 = __half22float2(*(__half2*)&v.z);
    float2 f3 = __half22float2(*(__half2*)&v.w);
    acc[0] += wv * f0.x; acc[1] += wv * f0.y;
    acc[2] += wv * f1.x; acc[3] += wv * f1.y;
    acc[4] += wv * f2.x; acc[5] += wv * f2.y;
    acc[6] += wv * f3.x; acc[7] += wv * f3.y;
}

// ---------------- CSR build -------------------------------------------------
__global__ void zero_cnt_kernel() {
    int i = blockIdx.x * blockDim.x + threadIdx.x;
    if (i < NN) g_cnt[i] = 0;
}

__global__ void count_kernel(const int* __restrict__ rows) {
    int i = blockIdx.x * blockDim.x + threadIdx.x;
    if (i < EE) atomicAdd(&g_cnt[rows[i]], 1);
}

// warp-shuffle hierarchical scan, 4 elems/thread, 4096 per iteration
__global__ void scan_kernel() {
    __shared__ int wsum[32];
    __shared__ int carry;
    int tid  = threadIdx.x;
    int lane = tid & 31;
    int wid  = tid >> 5;
    if (tid == 0) carry = 0;
    __syncthreads();
    for (int base = 0; base < NN; base += 4096) {
        int i0 = base + tid * 4;
        int v[4];
        #pragma unroll
        for (int k = 0; k < 4; k++) {
            int i = i0 + k;
            v[k] = (i < NN) ? g_cnt[i] : 0;
        }
        int s = v[0] + v[1] + v[2] + v[3];
        int sc = s;
        #pragma unroll
        for (int off = 1; off < 32; off <<= 1) {
            int t = __shfl_up_sync(0xffffffffu, sc, off);
            if (lane >= off) sc += t;
        }
        if (lane == 31) wsum[wid] = sc;
        __syncthreads();
        if (wid == 0) {
            int ws = wsum[lane];
            #pragma unroll
            for (int off = 1; off < 32; off <<= 1) {
                int t = __shfl_up_sync(0xffffffffu, ws, off);
                if (lane >= off) ws += t;
            }
            wsum[lane] = ws;
        }
        __syncthreads();
        int warpoff = (wid > 0) ? wsum[wid - 1] : 0;
        int excl = carry + warpoff + (sc - s);
        #pragma unroll
        for (int k = 0; k < 4; k++) {
            int i = i0 + k;
            if (i < NN) { g_rowptr[i] = excl; g_cnt[i] = excl; }
            excl += v[k];
        }
        __syncthreads();
        if (tid == 0) carry += wsum[31];
        __syncthreads();
    }
    if (tid == 0) g_rowptr[NN] = carry;
}

__global__ void scatter_kernel(const int* __restrict__ rows,
                               const int* __restrict__ cols,
                               const float* __restrict__ w) {
    int i = blockIdx.x * blockDim.x + threadIdx.x;
    if (i < EE) {
        int r = rows[i];
        int p = atomicAdd(&g_cnt[r], 1);
        g_col[p] = cols[i];
        g_wgt[p] = w[i];
    }
}

// ---------------- SpMM: y[r] = alpha * (L x)[r] + beta * s[r] (fp16 io) ----
// 128 threads = 4 warps = 4 rows per block; smem-staged edges (R9 config).
__global__ __launch_bounds__(128)
void spmm_kernel(const __half* __restrict__ x, int sx,
                 const __half* __restrict__ sub, int ss,
                 __half* __restrict__ y, int sy,
                 float alpha, float beta) {
    __shared__ int   sc[4][32];
    __shared__ float sw[4][32];
    int warp = threadIdx.x >> 5;
    int lane = threadIdx.x & 31;
    int r = blockIdx.x * 4 + warp;
    if (r >= NN) return;
    int beg = g_rowptr[r];
    int end = g_rowptr[r + 1];
    int fo = lane * 8;
    float acc[8] = {0.f, 0.f, 0.f, 0.f, 0.f, 0.f, 0.f, 0.f};
    for (int base = beg; base < end; base += 32) {
        int m = min(32, end - base);
        __syncwarp();
        if (lane < m) { sc[warp][lane] = g_col[base + lane]; sw[warp][lane] = g_wgt[base + lane]; }
        __syncwarp();
        #pragma unroll 4
        for (int j = 0; j < m; j++) {
            uint4 v = *(const uint4*)(x + (size_t)sc[warp][j] * sx + fo);
            acc_edge(acc, sw[warp][j], v);
        }
    }
    float o[8];
    #pragma unroll
    for (int i = 0; i < 8; i++) o[i] = alpha * acc[i];
    if (sub != nullptr) {
        uint4 sv = *(const uint4*)(sub + (size_t)r * ss + fo);
        float2 s0 = __half22float2(*(__half2*)&sv.x);
        float2 s1 = __half22float2(*(__half2*)&sv.y);
        float2 s2 = __half22float2(*(__half2*)&sv.z);
        float2 s3 = __half22float2(*(__half2*)&sv.w);
        o[0] += beta * s0.x; o[1] += beta * s0.y;
        o[2] += beta * s1.x; o[3] += beta * s1.y;
        o[4] += beta * s2.x; o[5] += beta * s2.y;
        o[6] += beta * s3.x; o[7] += beta * s3.y;
    }
    uint4 ov;
    *(__half2*)&ov.x = __floats2half2_rn(o[0], o[1]);
    *(__half2*)&ov.y = __floats2half2_rn(o[2], o[3]);
    *(__half2*)&ov.z = __floats2half2_rn(o[4], o[5]);
    *(__half2*)&ov.w = __floats2half2_rn(o[6], o[7]);
    *(uint4*)(y + (size_t)r * sy + fo) = ov;
}

// ---------------- final SpMM: out = 256*(L v + z0 - z2) + bias (fp32 out) --
__global__ __launch_bounds__(128)
void spmm_final_kernel(const __half* __restrict__ v,
                       const __half* __restrict__ Z,
                       const float* __restrict__ bias,
                       float* __restrict__ out) {
    __shared__ int   sc[4][32];
    __shared__ float sw[4][32];
    int warp = threadIdx.x >> 5;
    int lane = threadIdx.x & 31;
    int r = blockIdx.x * 4 + warp;
    if (r >= NN) return;
    int beg = g_rowptr[r];
    int end = g_rowptr[r + 1];
    int fo = lane * 8;
    float acc[8] = {0.f, 0.f, 0.f, 0.f, 0.f, 0.f, 0.f, 0.f};
    for (int base = beg; base < end; base += 32) {
        int m = min(32, end - base);
        __syncwarp();
        if (lane < m) { sc[warp][lane] = g_col[base + lane]; sw[warp][lane] = g_wgt[base + lane]; }
        __syncwarp();
        #pragma unroll 4
        for (int j = 0; j < m; j++) {
            uint4 vv = *(const uint4*)(v + (size_t)sc[warp][j] * FOUT + fo);
            acc_edge(acc, sw[warp][j], vv);
        }
    }
    uint4 z0v = *(const uint4*)(Z + (size_t)r * 768 + fo);
    uint4 z2v = *(const uint4*)(Z + (size_t)r * 768 + 512 + fo);
    const __half* z0 = (const __half*)&z0v;
    const __half* z2 = (const __half*)&z2v;
    float res[8];
    #pragma unroll
    for (int i = 0; i < 8; i++)
        res[i] = ACT_UNSCALE * (acc[i] + __half2float(z0[i]) - __half2float(z2[i]))
               + bias[fo + i];
    *(float4*)(out + (size_t)r * FOUT + fo)     = make_float4(res[0], res[1], res[2], res[3]);
    *(float4*)(out + (size_t)r * FOUT + fo + 4) = make_float4(res[4], res[5], res[6], res[7]);
}

// ---------------- weight de-interleave --------------------------------------
__global__ void split_kernel(const float* __restrict__ W, __half* __restrict__ B,
                             int F, int Hdim) {
    int idx = blockIdx.x * blockDim.x + threadIdx.x;
    int tot = 3 * F * Hdim;
    if (idx < tot) {
        int kk = idx % (3 * F);
        int o  = idx / (3 * F);
        int seg = kk / F;
        int f   = kk % F;
        B[idx] = __float2half_rn(W[(size_t)o * (3 * F) + f * 3 + seg]);
    }
}

__global__ void split4_kernel(const float* __restrict__ W, __half* __restrict__ B) {
    int idx = blockIdx.x * blockDim.x + threadIdx.x;
    if (idx < 768 * 512) {
        int k = idx % 512;
        int r = idx / 512;
        int seg = r / 256;
        int o   = r % 256;
        B[idx] = __float2half_rn(W[(size_t)o * 1536 + k * 3 + seg]);
    }
}

__global__ void round_kernel(const float* __restrict__ in, __half* __restrict__ out, int n) {
    int i = blockIdx.x * blockDim.x + threadIdx.x;
    if (i < n) out[i] = __float2half_rn(in[i] * ACT_SCALE);
}

// ---------------- mma.sync fp16 GEMM -----------------------------------------
__device__ __forceinline__ void load_tile(uint32_t sb, int s, int kt,
                                          const __half* __restrict__ A0,
                                          const __half* __restrict__ A1,
                                          const __half* __restrict__ A2,
                                          const __half* __restrict__ Bt,
                                          int n, int F, int Ktot,
                                          int bm, int bn, int tid) {
    int kg  = kt * BKH;
    int seg = kg / F;
    const __half* Ap = (seg == 0) ? A0 : ((seg == 1) ? A1 : A2);
    int kin = kg - seg * F;
    uint32_t abase = sb + s * STAGE_BYTES;
    uint32_t bbase = abase + 16384;
    #pragma unroll
    for (int i = 0; i < 4; i++) {
        int lin = i * 256 + tid;
        int row = lin >> 3;
        int c16 = lin & 7;
        int gr = bm + row;
        if (gr >= n) gr = n - 1;
        uint32_t off = row * 128 + c16 * 16;
        cp16(abase + SW(off), Ap + (size_t)gr * F + kin + c16 * 8);
    }
    #pragma unroll
    for (int i = 0; i < 4; i++) {
        int lin = i * 256 + tid;
        int row = lin >> 3;
        int c16 = lin & 7;
        uint32_t off = row * 128 + c16 * 16;
        cp16(bbase + SW(off), Bt + (size_t)(bn + row) * Ktot + kg + c16 * 8);
    }
}

template <bool RELU>
__global__ __launch_bounds__(256, 2)
void gemm_mma_kernel(const __half* __restrict__ A0,
                     const __half* __restrict__ A1,
                     const __half* __restrict__ A2,
                     const __half* __restrict__ Bt,
                     const float* __restrict__ bias,
                     __half* __restrict__ C,
                     int n, int F, int Ktot, int Hdim,
                     float bias_scale) {
    extern __shared__ char smem[];
    uint32_t sb = smem_u32(smem);
    int tid  = threadIdx.x;
    int lane = tid & 31;
    int wid  = tid >> 5;
    int wm = wid & 1;
    int wn = wid >> 1;
    int bn = blockIdx.x * BN;
    int bm = blockIdx.y * BM;
    int T = Ktot / BKH;

    float c[4][4][4];
    #pragma unroll
    for (int mi = 0; mi < 4; mi++)
        #pragma unroll
        for (int j = 0; j < 4; j++)
            #pragma unroll
            for (int e = 0; e < 4; e++) c[mi][j][e] = 0.f;

    #pragma unroll
    for (int p = 0; p < STAGES - 1; p++) {
        load_tile(sb, p, p, A0, A1, A2, Bt, n, F, Ktot, bm, bn, tid);
        asm volatile("cp.async.commit_group;" ::: "memory");
    }

    int lrow16 = lane & 15;
    int lhalf  = (lane >> 4) << 4;

    for (int t = 0; t < T; t++) {
        cp_wait_group<STAGES - 2>();
        __syncthreads();
        int pt = t + STAGES - 1;
        if (pt < T)
            load_tile(sb, pt % STAGES, pt, A0, A1, A2, Bt, n, F, Ktot, bm, bn, tid);
        asm volatile("cp.async.commit_group;" ::: "memory");

        uint32_t abase = sb + (t % STAGES) * STAGE_BYTES;
        uint32_t bbase = abase + 16384;

        #pragma unroll
        for (int ks = 0; ks < 4; ks++) {
            int colb = ks * 32 + lhalf;
            uint32_t a[4][4];
            #pragma unroll
            for (int mi = 0; mi < 4; mi++) {
                uint32_t off = (uint32_t)((wm * 64 + mi * 16 + lrow16) * 128 + colb);
                ldsm4(a[mi], abase + SW(off));
            }
            uint32_t b[2][4];
            #pragma unroll
            for (int p = 0; p < 2; p++) {
                uint32_t off = (uint32_t)((wn * 32 + p * 16 + lrow16) * 128 + colb);
                ldsm4(b[p], bbase + SW(off));
            }
            #pragma unroll
            for (int mi = 0; mi < 4; mi++)
                #pragma unroll
                for (int j = 0; j < 4; j++)
                    mma_f16(c[mi][j], a[mi], b[j >> 1][j & 1], b[j >> 1][2 + (j & 1)]);
        }
    }

    #pragma unroll
    for (int mi = 0; mi < 4; mi++) {
        int r0 = bm + wm * 64 + mi * 16 + (lane >> 2);
        #pragma unroll
        for (int j = 0; j < 4; j++) {
            int col = bn + wn * 32 + j * 8 + (lane & 3) * 2;
            float bb0 = bias[col] * bias_scale;
            float bb1 = bias[col + 1] * bias_scale;
            #pragma unroll
            for (int h = 0; h < 2; h++) {
                int r = r0 + h * 8;
                if (r < n) {
                    float v0 = c[mi][j][2 * h]     + bb0;
                    float v1 = c[mi][j][2 * h + 1] + bb1;
                    if (RELU) { v0 = fmaxf(v0, 0.f); v1 = fmaxf(v1, 0.f); }
                    __half2* Ch = (__half2*)(C + (size_t)r * Hdim + col);
                    *Ch = __floats2half2_rn(v0, v1);
                }
            }
        }
    }
}

// ---------------- host orchestration ---------------------------------------
struct Ctx {
    cudaStream_t s2;
    cudaEvent_t ev[2];
    Ctx() {
        cudaStreamCreateWithFlags(&s2, cudaStreamNonBlocking);
        for (int i = 0; i < 2; i++)
            cudaEventCreateWithFlags(&ev[i], cudaEventDisableTiming);
    }
};
static Ctx& ctx() { static Ctx c; return c; }

static void run_hidden_layer(const __half* in, int F,
                             const __half* Bm, const float* bias,
                             __half* X1, __half* X2, __half* outp) {
    for (int c = 0; c < F / 256; c++) {
        int f0 = c * 256;
        spmm_kernel<<<SPMM_GRID, 128>>>(in + f0, F, nullptr, 0, X1 + f0, F, 1.f, 0.f);
        spmm_kernel<<<SPMM_GRID, 128>>>(X1 + f0, F, in + f0, F, X2 + f0, F, 2.f, -1.f);
    }
    dim3 grid(HH / BN, (NN + BM - 1) / BM);
    gemm_mma_kernel<true><<<grid, 256, SMEM_BYTES>>>(
        in, X1, X2, Bm, bias, outp, NN, F, 3 * F, HH, ACT_SCALE);
}

extern "C" void kernel_launch(void* const* d_in, const int* in_sizes, int n_in,
                              void* d_out, int out_size) {
    const float* x    = (const float*)d_in[0];
    const int*   er   = (const int*)d_in[1];
    const int*   ec   = (const int*)d_in[2];
    const float* ew   = (const float*)d_in[3];
    const float* W1   = (const float*)d_in[4];
    const float* b1   = (const float*)d_in[5];
    const float* W2   = (const float*)d_in[6];
    const float* b2   = (const float*)d_in[7];
    const float* W3   = (const float*)d_in[8];
    const float* b3   = (const float*)d_in[9];
    const float* Wout = (const float*)d_in[10];
    const float* bout = (const float*)d_in[11];
    float* out = (float*)d_out;

    __half *X0h, *X1, *X2, *HA, *HB, *B1, *B2, *B3, *B4, *Z;
    float* dummy_bias;
    cudaGetSymbolAddress((void**)&X0h, g_X0h);
    cudaGetSymbolAddress((void**)&X1,  g_X1);
    cudaGetSymbolAddress((void**)&X2,  g_X2);
    cudaGetSymbolAddress((void**)&HA,  g_HA);
    cudaGetSymbolAddress((void**)&HB,  g_HB);
    cudaGetSymbolAddress((void**)&B1,  g_B1);
    cudaGetSymbolAddress((void**)&B2,  g_B2);
    cudaGetSymbolAddress((void**)&B3,  g_B3);
    cudaGetSymbolAddress((void**)&B4,  g_B4);
    cudaGetSymbolAddress((void**)&Z,   g_Z);
    cudaGetSymbolAddress((void**)&dummy_bias, g_wgt);

    cudaFuncSetAttribute(gemm_mma_kernel<true>,
                         cudaFuncAttributeMaxDynamicSharedMemorySize, SMEM_BYTES);
    cudaFuncSetAttribute(gemm_mma_kernel<false>,
                         cudaFuncAttributeMaxDynamicSharedMemorySize, SMEM_BYTES);

    Ctx& cx = ctx();
    cudaStream_t s2 = cx.s2;

    // ---- fork: side stream does round + weight splits (DRAM-light) ----
    cudaEventRecord(cx.ev[0], 0);
    cudaStreamWaitEvent(s2, cx.ev[0], 0);
    round_kernel<<<(NN * FIN + 255) / 256, 256, 0, s2>>>(x, X0h, NN * FIN);
    split_kernel<<<(3 * FIN * HH + 255) / 256, 256, 0, s2>>>(W1, B1, FIN, HH);
    split_kernel<<<(3 * HH * HH + 255) / 256, 256, 0, s2>>>(W2, B2, HH, HH);
    split_kernel<<<(3 * HH * HH + 255) / 256, 256, 0, s2>>>(W3, B3, HH, HH);
    split4_kernel<<<(768 * 512 + 255) / 256, 256, 0, s2>>>(Wout, B4);
    cudaEventRecord(cx.ev[1], s2);

    // ---- main: CSR build (concurrent) ----
    zero_cnt_kernel<<<(NN + 255) / 256, 256>>>();
    count_kernel<<<(EE + 255) / 256, 256>>>(er);
    scan_kernel<<<1, 1024>>>();
    scatter_kernel<<<(EE + 255) / 256, 256>>>(er, ec, ew);
    cudaStreamWaitEvent(0, cx.ev[1], 0);

    // ---- layers 1-3 ----
    run_hidden_layer(X0h, FIN, B1, b1, X1, X2, HA);
    run_hidden_layer(HA,  HH,  B2, b2, X1, X2, HB);
    run_hidden_layer(HB,  HH,  B3, b3, X1, X2, HA);

    // ---- layer 4 (weights-first) ----
    {
        dim3 grid(768 / BN, (NN + BM - 1) / BM);
        gemm_mma_kernel<false><<<grid, 256, SMEM_BYTES>>>(
            HA, HA, HA, B4, dummy_bias, Z, NN, HH, HH, 768, 0.f);
    }
    spmm_kernel<<<SPMM_GRID, 128>>>(Z + 512, 768, Z + 256, 768, X1, FOUT, 2.f, 1.f);
    spmm_final_kernel<<<SPMM_GRID, 128>>>(X1, Z, bout, out);
}

// round 14
// speedup vs baseline: 1.1108x; 1.0170x over previous
#include <cuda_runtime.h>
#include <cuda_fp16.h>
#include <cstdint>

#define NN   100000
#define EE   3200000
#define FIN  256
#define HH   512
#define FOUT 256

#define BM 128
#define BN 128
#define BKH 64
#define STAGES 3
#define STAGE_BYTES 32768
#define SMEM_BYTES (STAGES * STAGE_BYTES)

#define ACT_SCALE   0.00390625f   /* 2^-8 */
#define ACT_UNSCALE 256.0f

#define SW(o) ((o) ^ (((o) >> 3) & 0x70))
#define SPMM_GRID ((NN + 3) / 4)

// ---------------- scratch ---------------------------------------------------
__device__ __half g_X0h[(size_t)NN * FIN];
__device__ __half g_X1[(size_t)NN * HH];
__device__ __half g_X2[(size_t)NN * HH];
__device__ __half g_HA[(size_t)NN * HH];
__device__ __half g_HB[(size_t)NN * HH];
__device__ __half g_Z [(size_t)NN * 768];
__device__ __half g_B1[512 * 768];
__device__ __half g_B2[512 * 1536];
__device__ __half g_B3[512 * 1536];
__device__ __half g_B4[768 * 512];
__device__ int    g_rowptr[NN + 1];
__device__ int    g_cnt[NN];
__device__ int    g_col[EE];
__device__ float  g_wgt[EE];

// ---------------- helpers ---------------------------------------------------
__device__ __forceinline__ uint32_t smem_u32(const void* p) {
    uint32_t a;
    asm("{ .reg .u64 t; cvta.to.shared.u64 t, %1; cvt.u32.u64 %0, t; }" : "=r"(a) : "l"(p));
    return a;
}

template <int N>
__device__ __forceinline__ void cp_wait_group() {
    asm volatile("cp.async.wait_group %0;" :: "n"(N) : "memory");
}

__device__ __forceinline__ void cp16(uint32_t dst, const void* src) {
    asm volatile("cp.async.cg.shared.global [%0], [%1], 16;" :: "r"(dst), "l"(src));
}

__device__ __forceinline__ void ldsm4(uint32_t* r, uint32_t addr) {
    asm volatile("ldmatrix.sync.aligned.m8n8.x4.shared.b16 {%0,%1,%2,%3}, [%4];"
                 : "=r"(r[0]), "=r"(r[1]), "=r"(r[2]), "=r"(r[3]) : "r"(addr));
}

__device__ __forceinline__ void mma_f16(float* c, const uint32_t* a,
                                        uint32_t b0, uint32_t b1) {
    asm volatile(
        "mma.sync.aligned.m16n8k16.row.col.f32.f16.f16.f32 "
        "{%0,%1,%2,%3}, {%4,%5,%6,%7}, {%8,%9}, {%0,%1,%2,%3};"
        : "+f"(c[0]), "+f"(c[1]), "+f"(c[2]), "+f"(c[3])
        : "r"(a[0]), "r"(a[1]), "r"(a[2]), "r"(a[3]), "r"(b0), "r"(b1));
}

__device__ __forceinline__ void acc_edge(float* acc, float wv, uint4 v) {
    float2 f0 = __half22float2(*(__half2*)&v.x);
    float2 f1 = __half22float2(*(__half2*)&v.y);
    float2 f2 = __half22float2(*(__half2*)&v.z);
    float2 f3 = __half22float2(*(__half2*)&v.w);
    acc[0] += wv * f0.x; acc[1] += wv * f0.y;
    acc[2] += wv * f1.x; acc[3] += wv * f1.y;
    acc[4] += wv * f2.x; acc[5] += wv * f2.y;
    acc[6] += wv * f3.x; acc[7] += wv * f3.y;
}

// ---------------- CSR build -------------------------------------------------
__global__ void zero_cnt_kernel() {
    int i = blockIdx.x * blockDim.x + threadIdx.x;
    if (i < NN) g_cnt[i] = 0;
}

__global__ void count_kernel(const int* __restrict__ rows) {
    int i = blockIdx.x * blockDim.x + threadIdx.x;
    if (i < EE) atomicAdd(&g_cnt[rows[i]], 1);
}

// warp-shuffle hierarchical scan, 4 elems/thread, 4096 per iteration
__global__ void scan_kernel() {
    __shared__ int wsum[32];
    __shared__ int carry;
    int tid  = threadIdx.x;
    int lane = tid & 31;
    int wid  = tid >> 5;
    if (tid == 0) carry = 0;
    __syncthreads();
    for (int base = 0; base < NN; base += 4096) {
        int i0 = base + tid * 4;
        int v[4];
        #pragma unroll
        for (int k = 0; k < 4; k++) {
            int i = i0 + k;
            v[k] = (i < NN) ? g_cnt[i] : 0;
        }
        int s = v[0] + v[1] + v[2] + v[3];
        int sc = s;
        #pragma unroll
        for (int off = 1; off < 32; off <<= 1) {
            int t = __shfl_up_sync(0xffffffffu, sc, off);
            if (lane >= off) sc += t;
        }
        if (lane == 31) wsum[wid] = sc;
        __syncthreads();
        if (wid == 0) {
            int ws = wsum[lane];
            #pragma unroll
            for (int off = 1; off < 32; off <<= 1) {
                int t = __shfl_up_sync(0xffffffffu, ws, off);
                if (lane >= off) ws += t;
            }
            wsum[lane] = ws;
        }
        __syncthreads();
        int warpoff = (wid > 0) ? wsum[wid - 1] : 0;
        int excl = carry + warpoff + (sc - s);
        #pragma unroll
        for (int k = 0; k < 4; k++) {
            int i = i0 + k;
            if (i < NN) { g_rowptr[i] = excl; g_cnt[i] = excl; }
            excl += v[k];
        }
        __syncthreads();
        if (tid == 0) carry += wsum[31];
        __syncthreads();
    }
    if (tid == 0) g_rowptr[NN] = carry;
}

__global__ void scatter_kernel(const int* __restrict__ rows,
                               const int* __restrict__ cols,
                               const float* __restrict__ w) {
    int i = blockIdx.x * blockDim.x + threadIdx.x;
    if (i < EE) {
        int r = rows[i];
        int p = atomicAdd(&g_cnt[r], 1);
        g_col[p] = cols[i];
        g_wgt[p] = w[i];
    }
}

// ---------------- SpMM: y[r] = alpha * (L x)[r] + beta * s[r] (fp16 io) ----
// 128 threads = 4 warps = 4 rows per block; smem-staged edges.
__global__ __launch_bounds__(128)
void spmm_kernel(const __half* __restrict__ x, int sx,
                 const __half* __restrict__ sub, int ss,
                 __half* __restrict__ y, int sy,
                 float alpha, float beta) {
    __shared__ int   sc[4][32];
    __shared__ float sw[4][32];
    int warp = threadIdx.x >> 5;
    int lane = threadIdx.x & 31;
    int r = blockIdx.x * 4 + warp;
    if (r >= NN) return;
    int beg = g_rowptr[r];
    int end = g_rowptr[r + 1];
    int fo = lane * 8;
    float acc[8] = {0.f, 0.f, 0.f, 0.f, 0.f, 0.f, 0.f, 0.f};
    for (int base = beg; base < end; base += 32) {
        int m = min(32, end - base);
        __syncwarp();
        if (lane < m) { sc[warp][lane] = g_col[base + lane]; sw[warp][lane] = g_wgt[base + lane]; }
        __syncwarp();
        #pragma unroll 4
        for (int j = 0; j < m; j++) {
            uint4 v = *(const uint4*)(x + (size_t)sc[warp][j] * sx + fo);
            acc_edge(acc, sw[warp][j], v);
        }
    }
    float o[8];
    #pragma unroll
    for (int i = 0; i < 8; i++) o[i] = alpha * acc[i];
    if (sub != nullptr) {
        uint4 sv = *(const uint4*)(sub + (size_t)r * ss + fo);
        float2 s0 = __half22float2(*(__half2*)&sv.x);
        float2 s1 = __half22float2(*(__half2*)&sv.y);
        float2 s2 = __half22float2(*(__half2*)&sv.z);
        float2 s3 = __half22float2(*(__half2*)&sv.w);
        o[0] += beta * s0.x; o[1] += beta * s0.y;
        o[2] += beta * s1.x; o[3] += beta * s1.y;
        o[4] += beta * s2.x; o[5] += beta * s2.y;
        o[6] += beta * s3.x; o[7] += beta * s3.y;
    }
    uint4 ov;
    *(__half2*)&ov.x = __floats2half2_rn(o[0], o[1]);
    *(__half2*)&ov.y = __floats2half2_rn(o[2], o[3]);
    *(__half2*)&ov.z = __floats2half2_rn(o[4], o[5]);
    *(__half2*)&ov.w = __floats2half2_rn(o[6], o[7]);
    *(uint4*)(y + (size_t)r * sy + fo) = ov;
}

// ---------------- final SpMM: out = 256*(L v + z0') + bias (fp32 out) ------
// z0' = Z[:, 0:256] already holds h@(Wout0 - Wout2)^T (fold done in split4).
__global__ __launch_bounds__(128)
void spmm_final_kernel(const __half* __restrict__ v,
                       const __half* __restrict__ Z,
                       const float* __restrict__ bias,
                       float* __restrict__ out) {
    __shared__ int   sc[4][32];
    __shared__ float sw[4][32];
    int warp = threadIdx.x >> 5;
    int lane = threadIdx.x & 31;
    int r = blockIdx.x * 4 + warp;
    if (r >= NN) return;
    int beg = g_rowptr[r];
    int end = g_rowptr[r + 1];
    int fo = lane * 8;
    float acc[8] = {0.f, 0.f, 0.f, 0.f, 0.f, 0.f, 0.f, 0.f};
    for (int base = beg; base < end; base += 32) {
        int m = min(32, end - base);
        __syncwarp();
        if (lane < m) { sc[warp][lane] = g_col[base + lane]; sw[warp][lane] = g_wgt[base + lane]; }
        __syncwarp();
        #pragma unroll 4
        for (int j = 0; j < m; j++) {
            uint4 vv = *(const uint4*)(v + (size_t)sc[warp][j] * FOUT + fo);
            acc_edge(acc, sw[warp][j], vv);
        }
    }
    uint4 z0v = *(const uint4*)(Z + (size_t)r * 768 + fo);
    const __half* z0 = (const __half*)&z0v;
    float res[8];
    #pragma unroll
    for (int i = 0; i < 8; i++)
        res[i] = ACT_UNSCALE * (acc[i] + __half2float(z0[i])) + bias[fo + i];
    *(float4*)(out + (size_t)r * FOUT + fo)     = make_float4(res[0], res[1], res[2], res[3]);
    *(float4*)(out + (size_t)r * FOUT + fo + 4) = make_float4(res[4], res[5], res[6], res[7]);
}

// ---------------- weight de-interleave (seg0 folded: W0 - W2) ---------------
// Bt[o, seg*F+f]: seg0 -> W[o,f*3+0] - W[o,f*3+2]; seg1/2 -> W[o,f*3+seg]
__global__ void split_kernel(const float* __restrict__ W, __half* __restrict__ B,
                             int F, int Hdim) {
    int idx = blockIdx.x * blockDim.x + threadIdx.x;
    int tot = 3 * F * Hdim;
    if (idx < tot) {
        int kk = idx % (3 * F);
        int o  = idx / (3 * F);
        int seg = kk / F;
        int f   = kk % F;
        float val;
        if (seg == 0)
            val = W[(size_t)o * (3 * F) + f * 3] - W[(size_t)o * (3 * F) + f * 3 + 2];
        else
            val = W[(size_t)o * (3 * F) + f * 3 + seg];
        B[idx] = __float2half_rn(val);
    }
}

// layer 4: Bt4[seg*256 + o, k]: seg0 -> Wout0 - Wout2 fold, else Wout[o,k*3+seg]
__global__ void split4_kernel(const float* __restrict__ W, __half* __restrict__ B) {
    int idx = blockIdx.x * blockDim.x + threadIdx.x;
    if (idx < 768 * 512) {
        int k = idx % 512;
        int r = idx / 512;
        int seg = r / 256;
        int o   = r % 256;
        float val;
        if (seg == 0)
            val = W[(size_t)o * 1536 + k * 3] - W[(size_t)o * 1536 + k * 3 + 2];
        else
            val = W[(size_t)o * 1536 + k * 3 + seg];
        B[idx] = __float2half_rn(val);
    }
}

__global__ void round_kernel(const float* __restrict__ in, __half* __restrict__ out, int n) {
    int i = blockIdx.x * blockDim.x + threadIdx.x;
    if (i < n) out[i] = __float2half_rn(in[i] * ACT_SCALE);
}

// ---------------- mma.sync fp16 GEMM -----------------------------------------
__device__ __forceinline__ void load_tile(uint32_t sb, int s, int kt,
                                          const __half* __restrict__ A0,
                                          const __half* __restrict__ A1,
                                          const __half* __restrict__ A2,
                                          const __half* __restrict__ Bt,
                                          int n, int F, int Ktot,
                                          int bm, int bn, int tid) {
    int kg  = kt * BKH;
    int seg = kg / F;
    const __half* Ap = (seg == 0) ? A0 : ((seg == 1) ? A1 : A2);
    int kin = kg - seg * F;
    uint32_t abase = sb + s * STAGE_BYTES;
    uint32_t bbase = abase + 16384;
    #pragma unroll
    for (int i = 0; i < 4; i++) {
        int lin = i * 256 + tid;
        int row = lin >> 3;
        int c16 = lin & 7;
        int gr = bm + row;
        if (gr >= n) gr = n - 1;
        uint32_t off = row * 128 + c16 * 16;
        cp16(abase + SW(off), Ap + (size_t)gr * F + kin + c16 * 8);
    }
    #pragma unroll
    for (int i = 0; i < 4; i++) {
        int lin = i * 256 + tid;
        int row = lin >> 3;
        int c16 = lin & 7;
        uint32_t off = row * 128 + c16 * 16;
        cp16(bbase + SW(off), Bt + (size_t)(bn + row) * Ktot + kg + c16 * 8);
    }
}

template <bool RELU>
__global__ __launch_bounds__(256, 2)
void gemm_mma_kernel(const __half* __restrict__ A0,
                     const __half* __restrict__ A1,
                     const __half* __restrict__ A2,
                     const __half* __restrict__ Bt,
                     const float* __restrict__ bias,
                     __half* __restrict__ C,
                     int n, int F, int Ktot, int Hdim,
                     float bias_scale) {
    extern __shared__ char smem[];
    uint32_t sb = smem_u32(smem);
    int tid  = threadIdx.x;
    int lane = tid & 31;
    int wid  = tid >> 5;
    int wm = wid & 1;
    int wn = wid >> 1;
    int bn = blockIdx.x * BN;
    int bm = blockIdx.y * BM;
    int T = Ktot / BKH;

    float c[4][4][4];
    #pragma unroll
    for (int mi = 0; mi < 4; mi++)
        #pragma unroll
        for (int j = 0; j < 4; j++)
            #pragma unroll
            for (int e = 0; e < 4; e++) c[mi][j][e] = 0.f;

    #pragma unroll
    for (int p = 0; p < STAGES - 1; p++) {
        load_tile(sb, p, p, A0, A1, A2, Bt, n, F, Ktot, bm, bn, tid);
        asm volatile("cp.async.commit_group;" ::: "memory");
    }

    int lrow16 = lane & 15;
    int lhalf  = (lane >> 4) << 4;

    for (int t = 0; t < T; t++) {
        cp_wait_group<STAGES - 2>();
        __syncthreads();
        int pt = t + STAGES - 1;
        if (pt < T)
            load_tile(sb, pt % STAGES, pt, A0, A1, A2, Bt, n, F, Ktot, bm, bn, tid);
        asm volatile("cp.async.commit_group;" ::: "memory");

        uint32_t abase = sb + (t % STAGES) * STAGE_BYTES;
        uint32_t bbase = abase + 16384;

        #pragma unroll
        for (int ks = 0; ks < 4; ks++) {
            int colb = ks * 32 + lhalf;
            uint32_t a[4][4];
            #pragma unroll
            for (int mi = 0; mi < 4; mi++) {
                uint32_t off = (uint32_t)((wm * 64 + mi * 16 + lrow16) * 128 + colb);
                ldsm4(a[mi], abase + SW(off));
            }
            uint32_t b[2][4];
            #pragma unroll
            for (int p = 0; p < 2; p++) {
                uint32_t off = (uint32_t)((wn * 32 + p * 16 + lrow16) * 128 + colb);
                ldsm4(b[p], bbase + SW(off));
            }
            #pragma unroll
            for (int mi = 0; mi < 4; mi++)
                #pragma unroll
                for (int j = 0; j < 4; j++)
                    mma_f16(c[mi][j], a[mi], b[j >> 1][j & 1], b[j >> 1][2 + (j & 1)]);
        }
    }

    #pragma unroll
    for (int mi = 0; mi < 4; mi++) {
        int r0 = bm + wm * 64 + mi * 16 + (lane >> 2);
        #pragma unroll
        for (int j = 0; j < 4; j++) {
            int col = bn + wn * 32 + j * 8 + (lane & 3) * 2;
            float bb0 = bias[col] * bias_scale;
            float bb1 = bias[col + 1] * bias_scale;
            #pragma unroll
            for (int h = 0; h < 2; h++) {
                int r = r0 + h * 8;
                if (r < n) {
                    float v0 = c[mi][j][2 * h]     + bb0;
                    float v1 = c[mi][j][2 * h + 1] + bb1;
                    if (RELU) { v0 = fmaxf(v0, 0.f); v1 = fmaxf(v1, 0.f); }
                    __half2* Ch = (__half2*)(C + (size_t)r * Hdim + col);
                    *Ch = __floats2half2_rn(v0, v1);
                }
            }
        }
    }
}

// ---------------- host orchestration ---------------------------------------
struct Ctx {
    cudaStream_t s2;
    cudaEvent_t ev[2];
    Ctx() {
        cudaStreamCreateWithFlags(&s2, cudaStreamNonBlocking);
        for (int i = 0; i < 2; i++)
            cudaEventCreateWithFlags(&ev[i], cudaEventDisableTiming);
    }
};
static Ctx& ctx() { static Ctx c; return c; }

static void run_hidden_layer(const __half* in, int F,
                             const __half* Bm, const float* bias,
                             __half* X1, __half* X2, __half* outp) {
    for (int c = 0; c < F / 256; c++) {
        int f0 = c * 256;
        spmm_kernel<<<SPMM_GRID, 128>>>(in + f0, F, nullptr, 0, X1 + f0, F, 1.f, 0.f);
        // fold: X2' = 2*L*X1 (the -x term lives in the seg0 weights W0 - W2)
        spmm_kernel<<<SPMM_GRID, 128>>>(X1 + f0, F, nullptr, 0, X2 + f0, F, 2.f, 0.f);
    }
    dim3 grid(HH / BN, (NN + BM - 1) / BM);
    gemm_mma_kernel<true><<<grid, 256, SMEM_BYTES>>>(
        in, X1, X2, Bm, bias, outp, NN, F, 3 * F, HH, ACT_SCALE);
}

extern "C" void kernel_launch(void* const* d_in, const int* in_sizes, int n_in,
                              void* d_out, int out_size) {
    const float* x    = (const float*)d_in[0];
    const int*   er   = (const int*)d_in[1];
    const int*   ec   = (const int*)d_in[2];
    const float* ew   = (const float*)d_in[3];
    const float* W1   = (const float*)d_in[4];
    const float* b1   = (const float*)d_in[5];
    const float* W2   = (const float*)d_in[6];
    const float* b2   = (const float*)d_in[7];
    const float* W3   = (const float*)d_in[8];
    const float* b3   = (const float*)d_in[9];
    const float* Wout = (const float*)d_in[10];
    const float* bout = (const float*)d_in[11];
    float* out = (float*)d_out;

    __half *X0h, *X1, *X2, *HA, *HB, *B1, *B2, *B3, *B4, *Z;
    float* dummy_bias;
    cudaGetSymbolAddress((void**)&X0h, g_X0h);
    cudaGetSymbolAddress((void**)&X1,  g_X1);
    cudaGetSymbolAddress((void**)&X2,  g_X2);
    cudaGetSymbolAddress((void**)&HA,  g_HA);
    cudaGetSymbolAddress((void**)&HB,  g_HB);
    cudaGetSymbolAddress((void**)&B1,  g_B1);
    cudaGetSymbolAddress((void**)&B2,  g_B2);
    cudaGetSymbolAddress((void**)&B3,  g_B3);
    cudaGetSymbolAddress((void**)&B4,  g_B4);
    cudaGetSymbolAddress((void**)&Z,   g_Z);
    cudaGetSymbolAddress((void**)&dummy_bias, g_wgt);

    cudaFuncSetAttribute(gemm_mma_kernel<true>,
                         cudaFuncAttributeMaxDynamicSharedMemorySize, SMEM_BYTES);
    cudaFuncSetAttribute(gemm_mma_kernel<false>,
                         cudaFuncAttributeMaxDynamicSharedMemorySize, SMEM_BYTES);

    Ctx& cx = ctx();
    cudaStream_t s2 = cx.s2;

    // ---- fork: side stream does round + weight splits (DRAM-light) ----
    cudaEventRecord(cx.ev[0], 0);
    cudaStreamWaitEvent(s2, cx.ev[0], 0);
    round_kernel<<<(NN * FIN + 255) / 256, 256, 0, s2>>>(x, X0h, NN * FIN);
    split_kernel<<<(3 * FIN * HH + 255) / 256, 256, 0, s2>>>(W1, B1, FIN, HH);
    split_kernel<<<(3 * HH * HH + 255) / 256, 256, 0, s2>>>(W2, B2, HH, HH);
    split_kernel<<<(3 * HH * HH + 255) / 256, 256, 0, s2>>>(W3, B3, HH, HH);
    split4_kernel<<<(768 * 512 + 255) / 256, 256, 0, s2>>>(Wout, B4);
    cudaEventRecord(cx.ev[1], s2);

    // ---- main: CSR build (concurrent) ----
    zero_cnt_kernel<<<(NN + 255) / 256, 256>>>();
    count_kernel<<<(EE + 255) / 256, 256>>>(er);
    scan_kernel<<<1, 1024>>>();
    scatter_kernel<<<(EE + 255) / 256, 256>>>(er, ec, ew);
    cudaStreamWaitEvent(0, cx.ev[1], 0);

    // ---- layers 1-3 ----
    run_hidden_layer(X0h, FIN, B1, b1, X1, X2, HA);
    run_hidden_layer(HA,  HH,  B2, b2, X1, X2, HB);
    run_hidden_layer(HB,  HH,  B3, b3, X1, X2, HA);

    // ---- layer 4 (weights-first; z0' = h@(Wout0-Wout2)^T already folded) ----
    {
        dim3 grid(768 / BN, (NN + BM - 1) / BM);
        gemm_mma_kernel<false><<<grid, 256, SMEM_BYTES>>>(
            HA, HA, HA, B4, dummy_bias, Z, NN, HH, HH, 768, 0.f);
    }
    // v = z1 + 2 * L z2
    spmm_kernel<<<SPMM_GRID, 128>>>(Z + 512, 768, Z + 256, 768, X1, FOUT, 2.f, 1.f);
    // out = 256 * (L v + z0') + bout
    spmm_final_kernel<<<SPMM_GRID, 128>>>(X1, Z, bout, out);
}

// round 15
// speedup vs baseline: 1.1268x; 1.0144x over previous
#include <cuda_runtime.h>
#include <cuda_fp16.h>
#include <cstdint>

#define NN   100000
#define EE   3200000
#define FIN  256
#define HH   512
#define FOUT 256

#define BM 128
#define BN 128
#define BKH 64
#define STAGES 3
#define STAGE_BYTES 32768
#define SMEM_BYTES (STAGES * STAGE_BYTES)

#define ACT_SCALE   0.00390625f   /* 2^-8 */
#define ACT_UNSCALE 256.0f

#define SW(o) ((o) ^ (((o) >> 3) & 0x70))
#define SPMM_GRID ((NN + 3) / 4)

// ---------------- scratch ---------------------------------------------------
__device__ __half g_X0h[(size_t)NN * FIN];
__device__ __half g_X1[(size_t)NN * HH];
__device__ __half g_X2[(size_t)NN * HH];
__device__ __half g_HA[(size_t)NN * HH];
__device__ __half g_HB[(size_t)NN * HH];
__device__ __half g_Z [(size_t)NN * 768];
__device__ __half g_B1[512 * 768];
__device__ __half g_B2[512 * 1536];
__device__ __half g_B3[512 * 1536];
__device__ __half g_B4[768 * 512];
__device__ int    g_rowptr[NN + 1];
__device__ int    g_cnt[NN];
__device__ int2   g_edge[EE];        // packed (col, wgt-bits)

// ---------------- helpers ---------------------------------------------------
__device__ __forceinline__ uint32_t smem_u32(const void* p) {
    uint32_t a;
    asm("{ .reg .u64 t; cvta.to.shared.u64 t, %1; cvt.u32.u64 %0, t; }" : "=r"(a) : "l"(p));
    return a;
}

template <int N>
__device__ __forceinline__ void cp_wait_group() {
    asm volatile("cp.async.wait_group %0;" :: "n"(N) : "memory");
}

__device__ __forceinline__ void cp16(uint32_t dst, const void* src) {
    asm volatile("cp.async.cg.shared.global [%0], [%1], 16;" :: "r"(dst), "l"(src));
}

__device__ __forceinline__ void ldsm4(uint32_t* r, uint32_t addr) {
    asm volatile("ldmatrix.sync.aligned.m8n8.x4.shared.b16 {%0,%1,%2,%3}, [%4];"
                 : "=r"(r[0]), "=r"(r[1]), "=r"(r[2]), "=r"(r[3]) : "r"(addr));
}

__device__ __forceinline__ void mma_f16(float* c, const uint32_t* a,
                                        uint32_t b0, uint32_t b1) {
    asm volatile(
        "mma.sync.aligned.m16n8k16.row.col.f32.f16.f16.f32 "
        "{%0,%1,%2,%3}, {%4,%5,%6,%7}, {%8,%9}, {%0,%1,%2,%3};"
        : "+f"(c[0]), "+f"(c[1]), "+f"(c[2]), "+f"(c[3])
        : "r"(a[0]), "r"(a[1]), "r"(a[2]), "r"(a[3]), "r"(b0), "r"(b1));
}

__device__ __forceinline__ void acc_edge(float* acc, float wv, uint4 v) {
    float2 f0 = __half22float2(*(__half2*)&v.x);
    float2 f1 = __half22float2(*(__half2*)&v.y);
    float2 f2 = __half22float2(*(__half2*)&v.z);
    float2 f3 = __half22float2(*(__half2*)&v.w);
    acc[0] += wv * f0.x; acc[1] += wv * f0.y;
    acc[2] += wv * f1.x; acc[3] += wv * f1.y;
    acc[4] += wv * f2.x; acc[5] += wv * f2.y;
    acc[6] += wv * f3.x; acc[7] += wv * f3.y;
}

// ---------------- CSR build -------------------------------------------------
__global__ void zero_cnt_kernel() {
    int i = blockIdx.x * blockDim.x + threadIdx.x;
    if (i < NN) g_cnt[i] = 0;
}

__global__ void count_kernel(const int* __restrict__ rows) {
    int i = blockIdx.x * blockDim.x + threadIdx.x;
    if (i < EE) atomicAdd(&g_cnt[rows[i]], 1);
}

// warp-shuffle hierarchical scan, 4 elems/thread, 4096 per iteration
__global__ void scan_kernel() {
    __shared__ int wsum[32];
    __shared__ int carry;
    int tid  = threadIdx.x;
    int lane = tid & 31;
    int wid  = tid >> 5;
    if (tid == 0) carry = 0;
    __syncthreads();
    for (int base = 0; base < NN; base += 4096) {
        int i0 = base + tid * 4;
        int v[4];
        #pragma unroll
        for (int k = 0; k < 4; k++) {
            int i = i0 + k;
            v[k] = (i < NN) ? g_cnt[i] : 0;
        }
        int s = v[0] + v[1] + v[2] + v[3];
        int sc = s;
        #pragma unroll
        for (int off = 1; off < 32; off <<= 1) {
            int t = __shfl_up_sync(0xffffffffu, sc, off);
            if (lane >= off) sc += t;
        }
        if (lane == 31) wsum[wid] = sc;
        __syncthreads();
        if (wid == 0) {
            int ws = wsum[lane];
            #pragma unroll
            for (int off = 1; off < 32; off <<= 1) {
                int t = __shfl_up_sync(0xffffffffu, ws, off);
                if (lane >= off) ws += t;
            }
            wsum[lane] = ws;
        }
        __syncthreads();
        int warpoff = (wid > 0) ? wsum[wid - 1] : 0;
        int excl = carry + warpoff + (sc - s);
        #pragma unroll
        for (int k = 0; k < 4; k++) {
            int i = i0 + k;
            if (i < NN) { g_rowptr[i] = excl; g_cnt[i] = excl; }
            excl += v[k];
        }
        __syncthreads();
        if (tid == 0) carry += wsum[31];
        __syncthreads();
    }
    if (tid == 0) g_rowptr[NN] = carry;
}

__global__ void scatter_kernel(const int* __restrict__ rows,
                               const int* __restrict__ cols,
                               const float* __restrict__ w) {
    int i = blockIdx.x * blockDim.x + threadIdx.x;
    if (i < EE) {
        int r = rows[i];
        int p = atomicAdd(&g_cnt[r], 1);
        g_edge[p] = make_int2(cols[i], __float_as_int(w[i]));
    }
}

// ---------------- SpMM: y[r, chunk] = alpha*(L x)[r, chunk] + beta*s --------
// grid = (row-blocks, F/256); 4 warps = 4 rows per block; 256 features/chunk.
__global__ __launch_bounds__(128)
void spmm_kernel(const __half* __restrict__ x, int sx,
                 const __half* __restrict__ sub, int ss,
                 __half* __restrict__ y, int sy,
                 float alpha, float beta) {
    __shared__ int2 se[4][32];
    int warp = threadIdx.x >> 5;
    int lane = threadIdx.x & 31;
    int r = blockIdx.x * 4 + warp;
    if (r >= NN) return;
    int beg = g_rowptr[r];
    int end = g_rowptr[r + 1];
    int fo = blockIdx.y * 256 + lane * 8;
    float acc[8] = {0.f, 0.f, 0.f, 0.f, 0.f, 0.f, 0.f, 0.f};
    for (int base = beg; base < end; base += 32) {
        int m = min(32, end - base);
        __syncwarp();
        if (lane < m) se[warp][lane] = g_edge[base + lane];
        __syncwarp();
        #pragma unroll 4
        for (int j = 0; j < m; j++) {
            int2 e = se[warp][j];
            uint4 v = *(const uint4*)(x + (size_t)e.x * sx + fo);
            acc_edge(acc, __int_as_float(e.y), v);
        }
    }
    float o[8];
    #pragma unroll
    for (int i = 0; i < 8; i++) o[i] = alpha * acc[i];
    if (sub != nullptr) {
        uint4 sv = *(const uint4*)(sub + (size_t)r * ss + fo);
        float2 s0 = __half22float2(*(__half2*)&sv.x);
        float2 s1 = __half22float2(*(__half2*)&sv.y);
        float2 s2 = __half22float2(*(__half2*)&sv.z);
        float2 s3 = __half22float2(*(__half2*)&sv.w);
        o[0] += beta * s0.x; o[1] += beta * s0.y;
        o[2] += beta * s1.x; o[3] += beta * s1.y;
        o[4] += beta * s2.x; o[5] += beta * s2.y;
        o[6] += beta * s3.x; o[7] += beta * s3.y;
    }
    uint4 ov;
    *(__half2*)&ov.x = __floats2half2_rn(o[0], o[1]);
    *(__half2*)&ov.y = __floats2half2_rn(o[2], o[3]);
    *(__half2*)&ov.z = __floats2half2_rn(o[4], o[5]);
    *(__half2*)&ov.w = __floats2half2_rn(o[6], o[7]);
    *(uint4*)(y + (size_t)r * sy + fo) = ov;
}

// ---------------- final SpMM: out = 256*(L v + z0') + bias (fp32 out) ------
__global__ __launch_bounds__(128)
void spmm_final_kernel(const __half* __restrict__ v,
                       const __half* __restrict__ Z,
                       const float* __restrict__ bias,
                       float* __restrict__ out) {
    __shared__ int2 se[4][32];
    int warp = threadIdx.x >> 5;
    int lane = threadIdx.x & 31;
    int r = blockIdx.x * 4 + warp;
    if (r >= NN) return;
    int beg = g_rowptr[r];
    int end = g_rowptr[r + 1];
    int fo = lane * 8;
    float acc[8] = {0.f, 0.f, 0.f, 0.f, 0.f, 0.f, 0.f, 0.f};
    for (int base = beg; base < end; base += 32) {
        int m = min(32, end - base);
        __syncwarp();
        if (lane < m) se[warp][lane] = g_edge[base + lane];
        __syncwarp();
        #pragma unroll 4
        for (int j = 0; j < m; j++) {
            int2 e = se[warp][j];
            uint4 vv = *(const uint4*)(v + (size_t)e.x * FOUT + fo);
            acc_edge(acc, __int_as_float(e.y), vv);
        }
    }
    uint4 z0v = *(const uint4*)(Z + (size_t)r * 768 + fo);
    const __half* z0 = (const __half*)&z0v;
    float res[8];
    #pragma unroll
    for (int i = 0; i < 8; i++)
        res[i] = ACT_UNSCALE * (acc[i] + __half2float(z0[i])) + bias[fo + i];
    *(float4*)(out + (size_t)r * FOUT + fo)     = make_float4(res[0], res[1], res[2], res[3]);
    *(float4*)(out + (size_t)r * FOUT + fo + 4) = make_float4(res[4], res[5], res[6], res[7]);
}

// ---------------- weight de-interleave (seg0 folded: W0 - W2) ---------------
__global__ void split_kernel(const float* __restrict__ W, __half* __restrict__ B,
                             int F, int Hdim) {
    int idx = blockIdx.x * blockDim.x + threadIdx.x;
    int tot = 3 * F * Hdim;
    if (idx < tot) {
        int kk = idx % (3 * F);
        int o  = idx / (3 * F);
        int seg = kk / F;
        int f   = kk % F;
        float val;
        if (seg == 0)
            val = W[(size_t)o * (3 * F) + f * 3] - W[(size_t)o * (3 * F) + f * 3 + 2];
        else
            val = W[(size_t)o * (3 * F) + f * 3 + seg];
        B[idx] = __float2half_rn(val);
    }
}

__global__ void split4_kernel(const float* __restrict__ W, __half* __restrict__ B) {
    int idx = blockIdx.x * blockDim.x + threadIdx.x;
    if (idx < 768 * 512) {
        int k = idx % 512;
        int r = idx / 512;
        int seg = r / 256;
        int o   = r % 256;
        float val;
        if (seg == 0)
            val = W[(size_t)o * 1536 + k * 3] - W[(size_t)o * 1536 + k * 3 + 2];
        else
            val = W[(size_t)o * 1536 + k * 3 + seg];
        B[idx] = __float2half_rn(val);
    }
}

__global__ void round_kernel(const float* __restrict__ in, __half* __restrict__ out, int n) {
    int i = blockIdx.x * blockDim.x + threadIdx.x;
    if (i < n) out[i] = __float2half_rn(in[i] * ACT_SCALE);
}

// ---------------- mma.sync fp16 GEMM -----------------------------------------
__device__ __forceinline__ void load_tile(uint32_t sb, int s, int kt,
                                          const __half* __restrict__ A0,
                                          const __half* __restrict__ A1,
                                          const __half* __restrict__ A2,
                                          const __half* __restrict__ Bt,
                                          int n, int F, int Ktot,
                                          int bm, int bn, int tid) {
    int kg  = kt * BKH;
    int seg = kg / F;
    const __half* Ap = (seg == 0) ? A0 : ((seg == 1) ? A1 : A2);
    int kin = kg - seg * F;
    uint32_t abase = sb + s * STAGE_BYTES;
    uint32_t bbase = abase + 16384;
    #pragma unroll
    for (int i = 0; i < 4; i++) {
        int lin = i * 256 + tid;
        int row = lin >> 3;
        int c16 = lin & 7;
        int gr = bm + row;
        if (gr >= n) gr = n - 1;
        uint32_t off = row * 128 + c16 * 16;
        cp16(abase + SW(off), Ap + (size_t)gr * F + kin + c16 * 8);
    }
    #pragma unroll
    for (int i = 0; i < 4; i++) {
        int lin = i * 256 + tid;
        int row = lin >> 3;
        int c16 = lin & 7;
        uint32_t off = row * 128 + c16 * 16;
        cp16(bbase + SW(off), Bt + (size_t)(bn + row) * Ktot + kg + c16 * 8);
    }
}

template <bool RELU>
__global__ __launch_bounds__(256, 2)
void gemm_mma_kernel(const __half* __restrict__ A0,
                     const __half* __restrict__ A1,
                     const __half* __restrict__ A2,
                     const __half* __restrict__ Bt,
                     const float* __restrict__ bias,
                     __half* __restrict__ C,
                     int n, int F, int Ktot, int Hdim,
                     float bias_scale) {
    extern __shared__ char smem[];
    uint32_t sb = smem_u32(smem);
    int tid  = threadIdx.x;
    int lane = tid & 31;
    int wid  = tid >> 5;
    int wm = wid & 1;
    int wn = wid >> 1;
    int bn = blockIdx.x * BN;
    int bm = blockIdx.y * BM;
    int T = Ktot / BKH;

    float c[4][4][4];
    #pragma unroll
    for (int mi = 0; mi < 4; mi++)
        #pragma unroll
        for (int j = 0; j < 4; j++)
            #pragma unroll
            for (int e = 0; e < 4; e++) c[mi][j][e] = 0.f;

    #pragma unroll
    for (int p = 0; p < STAGES - 1; p++) {
        load_tile(sb, p, p, A0, A1, A2, Bt, n, F, Ktot, bm, bn, tid);
        asm volatile("cp.async.commit_group;" ::: "memory");
    }

    int lrow16 = lane & 15;
    int lhalf  = (lane >> 4) << 4;

    for (int t = 0; t < T; t++) {
        cp_wait_group<STAGES - 2>();
        __syncthreads();
        int pt = t + STAGES - 1;
        if (pt < T)
            load_tile(sb, pt % STAGES, pt, A0, A1, A2, Bt, n, F, Ktot, bm, bn, tid);
        asm volatile("cp.async.commit_group;" ::: "memory");

        uint32_t abase = sb + (t % STAGES) * STAGE_BYTES;
        uint32_t bbase = abase + 16384;

        #pragma unroll
        for (int ks = 0; ks < 4; ks++) {
            int colb = ks * 32 + lhalf;
            uint32_t a[4][4];
            #pragma unroll
            for (int mi = 0; mi < 4; mi++) {
                uint32_t off = (uint32_t)((wm * 64 + mi * 16 + lrow16) * 128 + colb);
                ldsm4(a[mi], abase + SW(off));
            }
            uint32_t b[2][4];
            #pragma unroll
            for (int p = 0; p < 2; p++) {
                uint32_t off = (uint32_t)((wn * 32 + p * 16 + lrow16) * 128 + colb);
                ldsm4(b[p], bbase + SW(off));
            }
            #pragma unroll
            for (int mi = 0; mi < 4; mi++)
                #pragma unroll
                for (int j = 0; j < 4; j++)
                    mma_f16(c[mi][j], a[mi], b[j >> 1][j & 1], b[j >> 1][2 + (j & 1)]);
        }
    }

    #pragma unroll
    for (int mi = 0; mi < 4; mi++) {
        int r0 = bm + wm * 64 + mi * 16 + (lane >> 2);
        #pragma unroll
        for (int j = 0; j < 4; j++) {
            int col = bn + wn * 32 + j * 8 + (lane & 3) * 2;
            float bb0 = bias[col] * bias_scale;
            float bb1 = bias[col + 1] * bias_scale;
            #pragma unroll
            for (int h = 0; h < 2; h++) {
                int r = r0 + h * 8;
                if (r < n) {
                    float v0 = c[mi][j][2 * h]     + bb0;
                    float v1 = c[mi][j][2 * h + 1] + bb1;
                    if (RELU) { v0 = fmaxf(v0, 0.f); v1 = fmaxf(v1, 0.f); }
                    __half2* Ch = (__half2*)(C + (size_t)r * Hdim + col);
                    *Ch = __floats2half2_rn(v0, v1);
                }
            }
        }
    }
}

// ---------------- host orchestration ---------------------------------------
struct Ctx {
    cudaStream_t s2;
    cudaEvent_t ev[2];
    Ctx() {
        cudaStreamCreateWithFlags(&s2, cudaStreamNonBlocking);
        for (int i = 0; i < 2; i++)
            cudaEventCreateWithFlags(&ev[i], cudaEventDisableTiming);
    }
};
static Ctx& ctx() { static Ctx c; return c; }

static void run_hidden_layer(const __half* in, int F,
                             const __half* Bm, const float* bias,
                             __half* X1, __half* X2, __half* outp) {
    dim3 sgrid(SPMM_GRID, F / 256);
    spmm_kernel<<<sgrid, 128>>>(in, F, nullptr, 0, X1, F, 1.f, 0.f);
    spmm_kernel<<<sgrid, 128>>>(X1, F, nullptr, 0, X2, F, 2.f, 0.f);
    dim3 grid(HH / BN, (NN + BM - 1) / BM);
    gemm_mma_kernel<true><<<grid, 256, SMEM_BYTES>>>(
        in, X1, X2, Bm, bias, outp, NN, F, 3 * F, HH, ACT_SCALE);
}

extern "C" void kernel_launch(void* const* d_in, const int* in_sizes, int n_in,
                              void* d_out, int out_size) {
    const float* x    = (const float*)d_in[0];
    const int*   er   = (const int*)d_in[1];
    const int*   ec   = (const int*)d_in[2];
    const float* ew   = (const float*)d_in[3];
    const float* W1   = (const float*)d_in[4];
    const float* b1   = (const float*)d_in[5];
    const float* W2   = (const float*)d_in[6];
    const float* b2   = (const float*)d_in[7];
    const float* W3   = (const float*)d_in[8];
    const float* b3   = (const float*)d_in[9];
    const float* Wout = (const float*)d_in[10];
    const float* bout = (const float*)d_in[11];
    float* out = (float*)d_out;

    __half *X0h, *X1, *X2, *HA, *HB, *B1, *B2, *B3, *B4, *Z;
    float* dummy_bias;
    cudaGetSymbolAddress((void**)&X0h, g_X0h);
    cudaGetSymbolAddress((void**)&X1,  g_X1);
    cudaGetSymbolAddress((void**)&X2,  g_X2);
    cudaGetSymbolAddress((void**)&HA,  g_HA);
    cudaGetSymbolAddress((void**)&HB,  g_HB);
    cudaGetSymbolAddress((void**)&B1,  g_B1);
    cudaGetSymbolAddress((void**)&B2,  g_B2);
    cudaGetSymbolAddress((void**)&B3,  g_B3);
    cudaGetSymbolAddress((void**)&B4,  g_B4);
    cudaGetSymbolAddress((void**)&Z,   g_Z);
    cudaGetSymbolAddress((void**)&dummy_bias, g_cnt);

    cudaFuncSetAttribute(gemm_mma_kernel<true>,
                         cudaFuncAttributeMaxDynamicSharedMemorySize, SMEM_BYTES);
    cudaFuncSetAttribute(gemm_mma_kernel<false>,
                         cudaFuncAttributeMaxDynamicSharedMemorySize, SMEM_BYTES);

    Ctx& cx = ctx();
    cudaStream_t s2 = cx.s2;

    // ---- fork: side stream does round + weight splits (DRAM-light) ----
    cudaEventRecord(cx.ev[0], 0);
    cudaStreamWaitEvent(s2, cx.ev[0], 0);
    round_kernel<<<(NN * FIN + 255) / 256, 256, 0, s2>>>(x, X0h, NN * FIN);
    split_kernel<<<(3 * FIN * HH + 255) / 256, 256, 0, s2>>>(W1, B1, FIN, HH);
    split_kernel<<<(3 * HH * HH + 255) / 256, 256, 0, s2>>>(W2, B2, HH, HH);
    split_kernel<<<(3 * HH * HH + 255) / 256, 256, 0, s2>>>(W3, B3, HH, HH);
    split4_kernel<<<(768 * 512 + 255) / 256, 256, 0, s2>>>(Wout, B4);
    cudaEventRecord(cx.ev[1], s2);

    // ---- main: CSR build (concurrent) ----
    zero_cnt_kernel<<<(NN + 255) / 256, 256>>>();
    count_kernel<<<(EE + 255) / 256, 256>>>(er);
    scan_kernel<<<1, 1024>>>();
    scatter_kernel<<<(EE + 255) / 256, 256>>>(er, ec, ew);
    cudaStreamWaitEvent(0, cx.ev[1], 0);

    // ---- layers 1-3 ----
    run_hidden_layer(X0h, FIN, B1, b1, X1, X2, HA);
    run_hidden_layer(HA,  HH,  B2, b2, X1, X2, HB);
    run_hidden_layer(HB,  HH,  B3, b3, X1, X2, HA);

    // ---- layer 4 (weights-first; z0' fold in split4) ----
    {
        dim3 grid(768 / BN, (NN + BM - 1) / BM);
        gemm_mma_kernel<false><<<grid, 256, SMEM_BYTES>>>(
            HA, HA, HA, B4, dummy_bias, Z, NN, HH, HH, 768, 0.f);
    }
    // v = z1 + 2 * L z2
    spmm_kernel<<<dim3(SPMM_GRID, 1), 128>>>(Z + 512, 768, Z + 256, 768, X1, FOUT, 2.f, 1.f);
    // out = 256 * (L v + z0') + bout
    spmm_final_kernel<<<SPMM_GRID, 128>>>(X1, Z, bout, out);
}